// round 10
// baseline (speedup 1.0000x reference)
#include <cuda_runtime.h>
#include <cstdint>

#define EMB 128
#define MAX_USERS 65536
#define MAX_GROUPS 4096
#define WARPS 8
#define THREADS (WARPS * 32)

// offsets scratch (allocation-free rule: __device__ globals)
__device__ int g_u_off[MAX_USERS + 1];
__device__ int g_g_off[MAX_GROUPS + 1];

// ---------------------------------------------------------------------------
// Prologue: O(n) adjacency scatter, 16 keys per thread (4 x int4, MLP=4).
//   u_off[u] = lower_bound(buid, u),  g_off[g] = lower_bound(ugid, g)
// ---------------------------------------------------------------------------
__device__ __forceinline__ void scatter16(const int* __restrict__ keys, int n,
                                          int* __restrict__ off, int max_key,
                                          int slot)
{
    const int base = slot * 16;
    if (base >= n) return;

    if (base + 16 <= n) {
        int4 a = *reinterpret_cast<const int4*>(keys + base + 0);
        int4 b = *reinterpret_cast<const int4*>(keys + base + 4);
        int4 c = *reinterpret_cast<const int4*>(keys + base + 8);
        int4 d = *reinterpret_cast<const int4*>(keys + base + 12);
        int k[16] = {a.x, a.y, a.z, a.w, b.x, b.y, b.z, b.w,
                     c.x, c.y, c.z, c.w, d.x, d.y, d.z, d.w};
        int prev = (base == 0) ? -1 : __ldg(keys + base - 1);
#pragma unroll
        for (int t = 0; t < 16; t++) {
            for (int u = prev + 1; u <= k[t]; u++) off[u] = base + t;
            prev = k[t];
        }
        if (base + 16 == n) {
            for (int u = prev + 1; u <= max_key; u++) off[u] = n;
        }
    } else {
        int prev = (base == 0) ? -1 : __ldg(keys + base - 1);
        for (int j = base; j < n; j++) {
            int cur = __ldg(keys + j);
            for (int u = prev + 1; u <= cur; u++) off[u] = j;
            prev = cur;
        }
        for (int u = prev + 1; u <= max_key; u++) off[u] = n;
    }
}

__global__ void __launch_bounds__(256) offsets_scatter_kernel(
    const int* __restrict__ buid, const int* __restrict__ ugid,
    int n_beh, int n_users, int num_groups)
{
    const int i = blockIdx.x * blockDim.x + threadIdx.x;
    const int n_beh_slots = (n_beh + 15) >> 4;

    if (i < n_beh_slots) {
        scatter16(buid, n_beh, g_u_off, n_users, i);
    } else {
        scatter16(ugid, n_users, g_g_off, num_groups, i - n_beh_slots);
    }
}

// ---------------------------------------------------------------------------
// Fused main kernel: one 256-thread CTA per group. 8 warps split the group's
// users contiguously (offsets precomputed). Each warp: gather item rows over
// each user's behavior segment (unroll x4, 2 accumulators), multiply by the
// user embedding (padding_idx=0), accumulate group partial in registers.
// Fixed-order smem tree reduce -> direct output store. No scratch round-trip.
// ---------------------------------------------------------------------------
__global__ void __launch_bounds__(THREADS) group_embedding_fused(
    const int* __restrict__ user_ids,
    const int* __restrict__ bitem,
    const float* __restrict__ bcnt,
    const float* __restrict__ user_table,
    const float* __restrict__ item_table,
    float* __restrict__ out)
{
    const int g    = blockIdx.x;
    const int lane = threadIdx.x & 31;
    const int w    = threadIdx.x >> 5;
    const int col  = lane * 4;

    __shared__ float s_part[WARPS * EMB];

    const int us = g_g_off[g];
    const int ue_end = g_g_off[g + 1];
    const int nu = ue_end - us;

    const int per = (nu + WARPS - 1) / WARPS;
    const int u0  = us + w * per;
    const int u1  = min(u0 + per, ue_end);

    float4 gacc = make_float4(0.f, 0.f, 0.f, 0.f);

    for (int u = u0; u < u1; u++) {
        const int uid = __ldg(user_ids + u);
        if (uid == 0) continue;

        const int s = __ldg(g_u_off + u);
        const int e = __ldg(g_u_off + u + 1);

        float4 a0 = make_float4(0.f, 0.f, 0.f, 0.f);
        float4 a1 = make_float4(0.f, 0.f, 0.f, 0.f);

        int j = s;
        for (; j + 3 < e; j += 4) {
            int   i0 = __ldcs(bitem + j + 0);
            int   i1 = __ldcs(bitem + j + 1);
            int   i2 = __ldcs(bitem + j + 2);
            int   i3 = __ldcs(bitem + j + 3);
            float c0 = __ldcs(bcnt + j + 0);
            float c1 = __ldcs(bcnt + j + 1);
            float c2 = __ldcs(bcnt + j + 2);
            float c3 = __ldcs(bcnt + j + 3);
            float4 v0 = *reinterpret_cast<const float4*>(item_table + (size_t)i0 * EMB + col);
            float4 v1 = *reinterpret_cast<const float4*>(item_table + (size_t)i1 * EMB + col);
            float4 v2 = *reinterpret_cast<const float4*>(item_table + (size_t)i2 * EMB + col);
            float4 v3 = *reinterpret_cast<const float4*>(item_table + (size_t)i3 * EMB + col);
            a0.x += c0 * v0.x; a0.y += c0 * v0.y; a0.z += c0 * v0.z; a0.w += c0 * v0.w;
            a1.x += c1 * v1.x; a1.y += c1 * v1.y; a1.z += c1 * v1.z; a1.w += c1 * v1.w;
            a0.x += c2 * v2.x; a0.y += c2 * v2.y; a0.z += c2 * v2.z; a0.w += c2 * v2.w;
            a1.x += c3 * v3.x; a1.y += c3 * v3.y; a1.z += c3 * v3.z; a1.w += c3 * v3.w;
        }
        for (; j < e; j++) {
            int   i0 = __ldcs(bitem + j);
            float c0 = __ldcs(bcnt + j);
            float4 v0 = *reinterpret_cast<const float4*>(item_table + (size_t)i0 * EMB + col);
            a0.x += c0 * v0.x; a0.y += c0 * v0.y; a0.z += c0 * v0.z; a0.w += c0 * v0.w;
        }

        float4 uev = *reinterpret_cast<const float4*>(user_table + (size_t)uid * EMB + col);
        gacc.x += (a0.x + a1.x) * uev.x;
        gacc.y += (a0.y + a1.y) * uev.y;
        gacc.z += (a0.z + a1.z) * uev.z;
        gacc.w += (a0.w + a1.w) * uev.w;
    }

    // fixed-order cross-warp reduce (deterministic)
    *reinterpret_cast<float4*>(s_part + w * EMB + col) = gacc;
    __syncthreads();

    if (w < 4) {  // 128 threads, one per output column
        const int t = threadIdx.x;
        float r = 0.f;
#pragma unroll
        for (int ww = 0; ww < WARPS; ww++) r += s_part[ww * EMB + t];
        out[(size_t)g * EMB + t] = r;
    }
}

extern "C" void kernel_launch(void* const* d_in, const int* in_sizes, int n_in,
                              void* d_out, int out_size)
{
    const int*   user_ids   = (const int*)  d_in[0];
    const int*   ugid       = (const int*)  d_in[1];
    const int*   bitem      = (const int*)  d_in[2];
    const float* bcnt       = (const float*)d_in[3];
    const int*   buid       = (const int*)  d_in[4];
    const float* user_table = (const float*)d_in[5];
    const float* item_table = (const float*)d_in[6];

    const int n_users    = in_sizes[0];
    const int n_beh      = in_sizes[2];
    const int num_groups = out_size / EMB;

    float* out = (float*)d_out;

    {
        int slots = ((n_beh + 15) >> 4) + ((n_users + 15) >> 4);
        offsets_scatter_kernel<<<(slots + 255) / 256, 256>>>(
            buid, ugid, n_beh, n_users, num_groups);
    }

    group_embedding_fused<<<num_groups, THREADS>>>(
        user_ids, bitem, bcnt, user_table, item_table, out);
}

// round 11
// speedup vs baseline: 1.0051x; 1.0051x over previous
#include <cuda_runtime.h>
#include <cstdint>

#define EMB 128
#define MAX_USERS 65536
#define MAX_GROUPS 4096
#define WARPS 8
#define THREADS (WARPS * 32)

// offsets scratch (allocation-free rule: __device__ globals)
__device__ int g_u_off[MAX_USERS + 1];
__device__ int g_g_off[MAX_GROUPS + 1];

// ---------------------------------------------------------------------------
// Prologue: O(n) adjacency scatter, 16 keys per thread (4 x int4, MLP=4).
//   u_off[u] = lower_bound(buid, u),  g_off[g] = lower_bound(ugid, g)
// ---------------------------------------------------------------------------
__device__ __forceinline__ void scatter16(const int* __restrict__ keys, int n,
                                          int* __restrict__ off, int max_key,
                                          int slot)
{
    const int base = slot * 16;
    if (base >= n) return;

    if (base + 16 <= n) {
        int4 a = *reinterpret_cast<const int4*>(keys + base + 0);
        int4 b = *reinterpret_cast<const int4*>(keys + base + 4);
        int4 c = *reinterpret_cast<const int4*>(keys + base + 8);
        int4 d = *reinterpret_cast<const int4*>(keys + base + 12);
        int k[16] = {a.x, a.y, a.z, a.w, b.x, b.y, b.z, b.w,
                     c.x, c.y, c.z, c.w, d.x, d.y, d.z, d.w};
        int prev = (base == 0) ? -1 : __ldg(keys + base - 1);
#pragma unroll
        for (int t = 0; t < 16; t++) {
            for (int u = prev + 1; u <= k[t]; u++) off[u] = base + t;
            prev = k[t];
        }
        if (base + 16 == n) {
            for (int u = prev + 1; u <= max_key; u++) off[u] = n;
        }
    } else {
        int prev = (base == 0) ? -1 : __ldg(keys + base - 1);
        for (int j = base; j < n; j++) {
            int cur = __ldg(keys + j);
            for (int u = prev + 1; u <= cur; u++) off[u] = j;
            prev = cur;
        }
        for (int u = prev + 1; u <= max_key; u++) off[u] = n;
    }
}

__global__ void __launch_bounds__(256) offsets_scatter_kernel(
    const int* __restrict__ buid, const int* __restrict__ ugid,
    int n_beh, int n_users, int num_groups)
{
    const int i = blockIdx.x * blockDim.x + threadIdx.x;
    const int n_beh_slots = (n_beh + 15) >> 4;

    if (i < n_beh_slots) {
        scatter16(buid, n_beh, g_u_off, n_users, i);
    } else {
        scatter16(ugid, n_users, g_g_off, num_groups, i - n_beh_slots);
    }
}

// ---------------------------------------------------------------------------
// Fused main kernel: one 256-thread CTA per group. 8 warps split the group's
// users contiguously (offsets precomputed). Each warp: gather item rows over
// each user's behavior segment (unroll x4, 2 accumulators), multiply by the
// user embedding (padding_idx=0), accumulate group partial in registers.
// Fixed-order smem tree reduce -> direct output store. No scratch round-trip.
// ---------------------------------------------------------------------------
__global__ void __launch_bounds__(THREADS) group_embedding_fused(
    const int* __restrict__ user_ids,
    const int* __restrict__ bitem,
    const float* __restrict__ bcnt,
    const float* __restrict__ user_table,
    const float* __restrict__ item_table,
    float* __restrict__ out)
{
    const int g    = blockIdx.x;
    const int lane = threadIdx.x & 31;
    const int w    = threadIdx.x >> 5;
    const int col  = lane * 4;

    __shared__ float s_part[WARPS * EMB];

    const int us = g_g_off[g];
    const int ue_end = g_g_off[g + 1];
    const int nu = ue_end - us;

    const int per = (nu + WARPS - 1) / WARPS;
    const int u0  = us + w * per;
    const int u1  = min(u0 + per, ue_end);

    float4 gacc = make_float4(0.f, 0.f, 0.f, 0.f);

    for (int u = u0; u < u1; u++) {
        const int uid = __ldg(user_ids + u);
        if (uid == 0) continue;

        const int s = __ldg(g_u_off + u);
        const int e = __ldg(g_u_off + u + 1);

        float4 a0 = make_float4(0.f, 0.f, 0.f, 0.f);
        float4 a1 = make_float4(0.f, 0.f, 0.f, 0.f);

        int j = s;
        for (; j + 3 < e; j += 4) {
            int   i0 = __ldcs(bitem + j + 0);
            int   i1 = __ldcs(bitem + j + 1);
            int   i2 = __ldcs(bitem + j + 2);
            int   i3 = __ldcs(bitem + j + 3);
            float c0 = __ldcs(bcnt + j + 0);
            float c1 = __ldcs(bcnt + j + 1);
            float c2 = __ldcs(bcnt + j + 2);
            float c3 = __ldcs(bcnt + j + 3);
            float4 v0 = *reinterpret_cast<const float4*>(item_table + (size_t)i0 * EMB + col);
            float4 v1 = *reinterpret_cast<const float4*>(item_table + (size_t)i1 * EMB + col);
            float4 v2 = *reinterpret_cast<const float4*>(item_table + (size_t)i2 * EMB + col);
            float4 v3 = *reinterpret_cast<const float4*>(item_table + (size_t)i3 * EMB + col);
            a0.x += c0 * v0.x; a0.y += c0 * v0.y; a0.z += c0 * v0.z; a0.w += c0 * v0.w;
            a1.x += c1 * v1.x; a1.y += c1 * v1.y; a1.z += c1 * v1.z; a1.w += c1 * v1.w;
            a0.x += c2 * v2.x; a0.y += c2 * v2.y; a0.z += c2 * v2.z; a0.w += c2 * v2.w;
            a1.x += c3 * v3.x; a1.y += c3 * v3.y; a1.z += c3 * v3.z; a1.w += c3 * v3.w;
        }
        for (; j < e; j++) {
            int   i0 = __ldcs(bitem + j);
            float c0 = __ldcs(bcnt + j);
            float4 v0 = *reinterpret_cast<const float4*>(item_table + (size_t)i0 * EMB + col);
            a0.x += c0 * v0.x; a0.y += c0 * v0.y; a0.z += c0 * v0.z; a0.w += c0 * v0.w;
        }

        float4 uev = *reinterpret_cast<const float4*>(user_table + (size_t)uid * EMB + col);
        gacc.x += (a0.x + a1.x) * uev.x;
        gacc.y += (a0.y + a1.y) * uev.y;
        gacc.z += (a0.z + a1.z) * uev.z;
        gacc.w += (a0.w + a1.w) * uev.w;
    }

    // fixed-order cross-warp reduce (deterministic)
    *reinterpret_cast<float4*>(s_part + w * EMB + col) = gacc;
    __syncthreads();

    if (w < 4) {  // 128 threads, one per output column
        const int t = threadIdx.x;
        float r = 0.f;
#pragma unroll
        for (int ww = 0; ww < WARPS; ww++) r += s_part[ww * EMB + t];
        out[(size_t)g * EMB + t] = r;
    }
}

extern "C" void kernel_launch(void* const* d_in, const int* in_sizes, int n_in,
                              void* d_out, int out_size)
{
    const int*   user_ids   = (const int*)  d_in[0];
    const int*   ugid       = (const int*)  d_in[1];
    const int*   bitem      = (const int*)  d_in[2];
    const float* bcnt       = (const float*)d_in[3];
    const int*   buid       = (const int*)  d_in[4];
    const float* user_table = (const float*)d_in[5];
    const float* item_table = (const float*)d_in[6];

    const int n_users    = in_sizes[0];
    const int n_beh      = in_sizes[2];
    const int num_groups = out_size / EMB;

    float* out = (float*)d_out;

    {
        int slots = ((n_beh + 15) >> 4) + ((n_users + 15) >> 4);
        offsets_scatter_kernel<<<(slots + 255) / 256, 256>>>(
            buid, ugid, n_beh, n_users, num_groups);
    }

    group_embedding_fused<<<num_groups, THREADS>>>(
        user_ids, bitem, bcnt, user_table, item_table, out);
}